// round 4
// baseline (speedup 1.0000x reference)
#include <cuda_runtime.h>
#include <cuda_fp16.h>
#include <cstdint>

// ---------------- problem constants ----------------
static constexpr int BB = 16;
static constexpr int II = 256;   // in channels (= GEMM K)
static constexpr int OO = 256;   // out channels (= GEMM M)
static constexpr int TT = 512;
static constexpr int LL = 8192;  // length (= GEMM N)
static constexpr int KW = 7;

// ---------------- tiling ----------------
static constexpr int TN = 128;       // L per CTA
static constexpr int KC = 64;        // K chunk
static constexpr int NCH = II / KC;  // 4 chunks
static constexpr int NTHR = 512;     // 16 warps

// ---------------- smem layout (bytes) ----------------
// sA: [256 m][64 k] fp16, 128B rows, SW128 generic swizzle        = 32768
// sB: [64 ch][128 n] fp16, 256B rows, swizzle ^((ch&7)<<4)        = 16384
// sbx: [64 ch][136 n] fp32 (l0-4 .. l0+131), 544B rows            = 34816
static constexpr int SA0 = 0;
static constexpr int SA1 = 32768;
static constexpr int SB0 = 65536;
static constexpr int SB1 = 81920;
static constexpr int SX0 = 98304;
static constexpr int SX1 = 133120;
static constexpr int SWC = 167936;                 // conv weights 256*7 fp32
static constexpr int SM_TOTAL = SWC + II * KW * 4; // 175104

// ---------------- device scratch ----------------
__device__ __half g_bw[(size_t)BB * OO * II];
__device__ float g_scale[BB * II];

// ---------------- helpers ----------------
__device__ __forceinline__ uint32_t smem_u32(const void* p) {
    uint32_t a;
    asm("{ .reg .u64 t; cvta.to.shared.u64 t, %1; cvt.u32.u64 %0, t; }" : "=r"(a) : "l"(p));
    return a;
}

__device__ __forceinline__ void cp16(uint32_t dst, const void* src, int sz) {
    asm volatile("cp.async.cg.shared.global [%0], [%1], 16, %2;"
                 :: "r"(dst), "l"(src), "r"(sz) : "memory");
}
__device__ __forceinline__ void cp_commit() {
    asm volatile("cp.async.commit_group;" ::: "memory");
}
__device__ __forceinline__ void cp_wait0() {
    asm volatile("cp.async.wait_group 0;" ::: "memory");
}

__device__ __forceinline__ void ldsm_x4(uint32_t* r, uint32_t addr) {
    asm volatile("ldmatrix.sync.aligned.m8n8.x4.shared.b16 {%0,%1,%2,%3}, [%4];"
                 : "=r"(r[0]), "=r"(r[1]), "=r"(r[2]), "=r"(r[3]) : "r"(addr));
}
__device__ __forceinline__ void ldsm_x4_t(uint32_t* r, uint32_t addr) {
    asm volatile("ldmatrix.sync.aligned.m8n8.x4.trans.shared.b16 {%0,%1,%2,%3}, [%4];"
                 : "=r"(r[0]), "=r"(r[1]), "=r"(r[2]), "=r"(r[3]) : "r"(addr));
}

__device__ __forceinline__ void mma16816(float* c, const uint32_t* a, const uint32_t* b) {
    asm volatile(
        "mma.sync.aligned.m16n8k16.row.col.f32.f16.f16.f32 "
        "{%0,%1,%2,%3}, {%4,%5,%6,%7}, {%8,%9}, {%0,%1,%2,%3};"
        : "+f"(c[0]), "+f"(c[1]), "+f"(c[2]), "+f"(c[3])
        : "r"(a[0]), "r"(a[1]), "r"(a[2]), "r"(a[3]), "r"(b[0]), "r"(b[1]));
}

#define SWZA(off) ((off) ^ (((off) >> 3) & 0x70))

// ---------------- kernel 1: scale = t @ mod_w^T + mod_b + 1 ----------------
__global__ void k_scale(const float* __restrict__ t, const float* __restrict__ mod_w,
                        const float* __restrict__ mod_b) {
    int b = blockIdx.x;
    int wid = threadIdx.x >> 5, lane = threadIdx.x & 31;
    const float* tb = t + b * TT;
    for (int i = wid; i < II; i += 8) {
        const float* wr = mod_w + (size_t)i * TT;
        float s = 0.f;
        for (int k = lane; k < TT; k += 32) s += tb[k] * wr[k];
        #pragma unroll
        for (int o = 16; o; o >>= 1) s += __shfl_xor_sync(0xffffffffu, s, o);
        if (lane == 0) g_scale[b * II + i] = s + mod_b[i] + 1.0f;
    }
}

// ---------------- kernel 2: modulated + demodulated weights (fp16) ----------------
__global__ void k_bw(const float* __restrict__ proj_w) {
    int b = blockIdx.y;
    int o0 = blockIdx.x * 32;
    __shared__ float sc[II];
    int tid = threadIdx.x;
    if (tid < II) sc[tid] = g_scale[b * II + tid];
    __syncthreads();
    int wid = tid >> 5, lane = tid & 31;
    for (int o = o0 + wid; o < o0 + 32; o += 8) {
        const float* pr = proj_w + (size_t)o * II;
        float wv[8];
        float ss = 0.f;
        #pragma unroll
        for (int m = 0; m < 8; m++) {
            float w = pr[lane + 32 * m] * sc[lane + 32 * m];
            wv[m] = w;
            ss += w * w;
        }
        #pragma unroll
        for (int off = 16; off; off >>= 1) ss += __shfl_xor_sync(0xffffffffu, ss, off);
        float d = rsqrtf(ss + 1e-8f);
        size_t base = ((size_t)b * OO + o) * II;
        #pragma unroll
        for (int m = 0; m < 8; m++)
            g_bw[base + lane + 32 * m] = __float2half_rn(wv[m] * d);
    }
}

// ---------------- kernel 3: fused conv + HMMA GEMM ----------------
__global__ void __launch_bounds__(NTHR, 1)
k_main(const float* __restrict__ bx, const float* __restrict__ conv_w,
       const float* __restrict__ proj_b, float* __restrict__ out) {
    extern __shared__ char smem[];
    const uint32_t sbu = smem_u32(smem);
    const int tid = threadIdx.x;
    const int wid = tid >> 5, lane = tid & 31;
    const int l0 = blockIdx.x * TN;
    const int b = blockIdx.y;
    const size_t bwb = (size_t)b * OO * II;

    // conv weights -> smem
    float* wc = (float*)(smem + SWC);
    for (int i = tid; i < II * KW; i += NTHR) wc[i] = conv_w[i];

    // ---- chunk loader: A tile (g_bw fp16) + bx rows, via cp.async ----
    auto issue_chunk = [&](int c, int buf) {
        const uint32_t sA = sbu + (buf ? SA1 : SA0);
        const __half* asrc = g_bw + bwb + c * KC;
        #pragma unroll
        for (int i = tid; i < 2048; i += NTHR) {      // 256 rows * 8 x 16B
            int m = i >> 3, q = i & 7;
            uint32_t off = m * 128 + q * 16;
            cp16(sA + SWZA(off), asrc + (size_t)m * II + q * 8, 16);
        }
        const uint32_t sX = sbu + (buf ? SX1 : SX0);
        const float* xsrc = bx + ((size_t)(b * II + c * KC)) * LL;
        for (int i = tid; i < 2176; i += NTHR) {      // 64 rows * 34 x 16B
            int r = i / 34, q = i - r * 34;
            int s = l0 - 4 + q * 4;
            bool ok = (s >= 0) && (s < LL);
            cp16(sX + r * 544 + q * 16, xsrc + (size_t)r * LL + (ok ? s : 0), ok ? 16 : 0);
        }
    };

    issue_chunk(0, 0);
    cp_commit();

    float acc[2][8][4];
    #pragma unroll
    for (int i = 0; i < 2; i++)
        #pragma unroll
        for (int j = 0; j < 8; j++)
            #pragma unroll
            for (int k = 0; k < 4; k++) acc[i][j][k] = 0.f;

    const int m0w = (wid & 7) * 32;    // warp M offset (A rows)
    const int n0w = (wid >> 3) * 64;   // warp N offset (L cols)

    for (int c = 0; c < NCH; c++) {
        const int buf = c & 1;
        cp_wait0();
        __syncthreads();

        // ---- conv: sbx (fp32) -> sB (fp16, k-major rows) ----
        {
            char* sBw = smem + (buf ? SB1 : SB0);
            const float* sbx = (const float*)(smem + (buf ? SX1 : SX0));
            const int n0 = lane * 4;              // output cols n0..n0+3
            #pragma unroll
            for (int cc = 0; cc < 4; cc++) {
                const int chl = wid * 4 + cc;     // 0..63
                const int chg = c * KC + chl;
                float cw[KW];
                #pragma unroll
                for (int j = 0; j < KW; j++) cw[j] = wc[chg * KW + j];
                const float4* r4 = (const float4*)(sbx + chl * 136);
                float4 q0 = r4[lane];             // sbx idx n0 .. n0+3
                float4 q1 = r4[lane + 1];         // n0+4 .. n0+7
                float4 q2 = r4[lane + 2];         // n0+8 .. n0+11
                float w[12] = {q0.x, q0.y, q0.z, q0.w, q1.x, q1.y, q1.z, q1.w,
                               q2.x, q2.y, q2.z, q2.w};
                // output n needs sbx idx (n+1 .. n+7)
                float a0 = 0.f, a1 = 0.f, a2 = 0.f, a3 = 0.f;
                #pragma unroll
                for (int j = 0; j < KW; j++) {
                    a0 += cw[j] * w[j + 1];
                    a1 += cw[j] * w[j + 2];
                    a2 += cw[j] * w[j + 3];
                    a3 += cw[j] * w[j + 4];
                }
                __half2 h01 = __halves2half2(__float2half_rn(a0), __float2half_rn(a1));
                __half2 h23 = __halves2half2(__float2half_rn(a2), __float2half_rn(a3));
                uint32_t off = (uint32_t)(chl * 256 + n0 * 2);
                uint2 v;
                v.x = *reinterpret_cast<uint32_t*>(&h01);
                v.y = *reinterpret_cast<uint32_t*>(&h23);
                *reinterpret_cast<uint2*>(sBw + (off ^ ((chl & 7) << 4))) = v;
            }
        }

        if (c < NCH - 1) { issue_chunk(c + 1, buf ^ 1); cp_commit(); }
        __syncthreads();

        // ---- MMA phase ----
        {
            const uint32_t sA = sbu + (buf ? SA1 : SA0);
            const uint32_t sBt = sbu + (buf ? SB1 : SB0);
            const int g = lane >> 3;       // ldmatrix address group 0..3
            const int li = lane & 7;
            #pragma unroll
            for (int ks = 0; ks < 4; ks++) {
                uint32_t afr[2][4];
                #pragma unroll
                for (int mt = 0; mt < 2; mt++) {
                    int row = m0w + mt * 16 + li + (g & 1) * 8;
                    int kh = ks * 16 + (g >> 1) * 8;
                    uint32_t off = row * 128 + kh * 2;
                    ldsm_x4(afr[mt], sA + SWZA(off));
                }
                uint32_t bfr[8][2];
                #pragma unroll
                for (int np = 0; np < 4; np++) {
                    int krow = ks * 16 + li + (g & 1) * 8;
                    int ncol = n0w + np * 16 + (g >> 1) * 8;
                    uint32_t off = krow * 256 + ncol * 2;
                    uint32_t r[4];
                    ldsm_x4_t(r, sBt + (off ^ ((krow & 7) << 4)));
                    bfr[2 * np][0] = r[0]; bfr[2 * np][1] = r[1];
                    bfr[2 * np + 1][0] = r[2]; bfr[2 * np + 1][1] = r[3];
                }
                #pragma unroll
                for (int mt = 0; mt < 2; mt++)
                    #pragma unroll
                    for (int nt = 0; nt < 8; nt++)
                        mma16816(acc[mt][nt], afr[mt], bfr[nt]);
            }
        }
        __syncthreads();
    }

    // ---- epilogue: direct float2 stores + bias ----
    const int rbase = m0w + (lane >> 2);
    const int cbase = n0w + 2 * (lane & 3);
    #pragma unroll
    for (int mt = 0; mt < 2; mt++) {
        int ra = rbase + mt * 16;
        int rb = ra + 8;
        float biasa = __ldg(proj_b + ra);
        float biasb = __ldg(proj_b + rb);
        float* pa = out + ((size_t)(b * OO + ra)) * LL + l0 + cbase;
        float* pb = out + ((size_t)(b * OO + rb)) * LL + l0 + cbase;
        #pragma unroll
        for (int nt = 0; nt < 8; nt++) {
            float2 v0 = {acc[mt][nt][0] + biasa, acc[mt][nt][1] + biasa};
            float2 v1 = {acc[mt][nt][2] + biasb, acc[mt][nt][3] + biasb};
            *reinterpret_cast<float2*>(pa + nt * 8) = v0;
            *reinterpret_cast<float2*>(pb + nt * 8) = v1;
        }
    }
}

// ---------------- launch ----------------
extern "C" void kernel_launch(void* const* d_in, const int* in_sizes, int n_in,
                              void* d_out, int out_size) {
    (void)in_sizes; (void)n_in; (void)out_size;
    const float* bx     = (const float*)d_in[0];
    const float* t      = (const float*)d_in[1];
    const float* conv_w = (const float*)d_in[2];
    const float* proj_w = (const float*)d_in[3];
    const float* proj_b = (const float*)d_in[4];
    const float* mod_w  = (const float*)d_in[5];
    const float* mod_b  = (const float*)d_in[6];
    float* out = (float*)d_out;

    cudaFuncSetAttribute(k_main, cudaFuncAttributeMaxDynamicSharedMemorySize, SM_TOTAL);

    k_scale<<<BB, 256>>>(t, mod_w, mod_b);
    k_bw<<<dim3(OO / 32, BB), 256>>>(proj_w);
    k_main<<<dim3(LL / TN, BB), NTHR, SM_TOTAL>>>(bx, conv_w, proj_b, out);
}

// round 5
// speedup vs baseline: 1.4407x; 1.4407x over previous
#include <cuda_runtime.h>
#include <cuda_fp16.h>
#include <cstdint>

// ---------------- problem constants ----------------
static constexpr int BB = 16;
static constexpr int II = 256;   // in channels (= GEMM K)
static constexpr int OO = 256;   // out channels (= GEMM M)
static constexpr int TT = 512;
static constexpr int LL = 8192;  // length (= GEMM N)
static constexpr int KW = 7;

// ---------------- tiling ----------------
static constexpr int TN = 128;       // L per CTA
static constexpr int KC = 64;        // K chunk
static constexpr int NCH = II / KC;  // 4 chunks
static constexpr int NTHR = 512;     // 16 warps

// ---------------- smem layout (bytes) ----------------
static constexpr int SA0 = 0;
static constexpr int SA1 = 32768;
static constexpr int SB0 = 65536;
static constexpr int SB1 = 81920;
static constexpr int SX0 = 98304;
static constexpr int SX1 = 133120;
static constexpr int SWC = 167936;                 // conv weights 256*7 fp32
static constexpr int SM_TOTAL = SWC + II * KW * 4; // 175104

// ---------------- device scratch ----------------
__device__ __half g_bw[(size_t)BB * OO * II];
__device__ float g_scale[BB * II];

// ---------------- helpers ----------------
__device__ __forceinline__ uint32_t smem_u32(const void* p) {
    uint32_t a;
    asm("{ .reg .u64 t; cvta.to.shared.u64 t, %1; cvt.u32.u64 %0, t; }" : "=r"(a) : "l"(p));
    return a;
}

__device__ __forceinline__ void cp16(uint32_t dst, const void* src, int sz) {
    asm volatile("cp.async.cg.shared.global [%0], [%1], 16, %2;"
                 :: "r"(dst), "l"(src), "r"(sz) : "memory");
}
__device__ __forceinline__ void cp_commit() {
    asm volatile("cp.async.commit_group;" ::: "memory");
}
__device__ __forceinline__ void cp_wait0() {
    asm volatile("cp.async.wait_group 0;" ::: "memory");
}

__device__ __forceinline__ void ldsm_x4(uint32_t* r, uint32_t addr) {
    asm volatile("ldmatrix.sync.aligned.m8n8.x4.shared.b16 {%0,%1,%2,%3}, [%4];"
                 : "=r"(r[0]), "=r"(r[1]), "=r"(r[2]), "=r"(r[3]) : "r"(addr));
}
__device__ __forceinline__ void ldsm_x4_t(uint32_t* r, uint32_t addr) {
    asm volatile("ldmatrix.sync.aligned.m8n8.x4.trans.shared.b16 {%0,%1,%2,%3}, [%4];"
                 : "=r"(r[0]), "=r"(r[1]), "=r"(r[2]), "=r"(r[3]) : "r"(addr));
}

__device__ __forceinline__ void mma16816(float* c, const uint32_t* a, const uint32_t* b) {
    asm volatile(
        "mma.sync.aligned.m16n8k16.row.col.f32.f16.f16.f32 "
        "{%0,%1,%2,%3}, {%4,%5,%6,%7}, {%8,%9}, {%0,%1,%2,%3};"
        : "+f"(c[0]), "+f"(c[1]), "+f"(c[2]), "+f"(c[3])
        : "r"(a[0]), "r"(a[1]), "r"(a[2]), "r"(a[3]), "r"(b[0]), "r"(b[1]));
}

#define SWZA(off) ((off) ^ (((off) >> 3) & 0x70))

// ---------------- kernel 1: scale = t @ mod_w^T + mod_b + 1 ----------------
// one warp per (b, i): grid (II/8, BB), 8 warps per CTA
__global__ void k_scale(const float* __restrict__ t, const float* __restrict__ mod_w,
                        const float* __restrict__ mod_b) {
    const int b = blockIdx.y;
    const int i = blockIdx.x * 8 + (threadIdx.x >> 5);
    const int lane = threadIdx.x & 31;
    const float* tb = t + b * TT;
    const float* wr = mod_w + (size_t)i * TT;
    float s = 0.f;
    #pragma unroll
    for (int k = lane; k < TT; k += 32) s += tb[k] * wr[k];
    #pragma unroll
    for (int o = 16; o; o >>= 1) s += __shfl_xor_sync(0xffffffffu, s, o);
    if (lane == 0) g_scale[b * II + i] = s + mod_b[i] + 1.0f;
}

// ---------------- kernel 2: modulated + demodulated weights (fp16) ----------------
__global__ void k_bw(const float* __restrict__ proj_w) {
    int b = blockIdx.y;
    int o0 = blockIdx.x * 32;
    __shared__ float sc[II];
    int tid = threadIdx.x;
    if (tid < II) sc[tid] = g_scale[b * II + tid];
    __syncthreads();
    int wid = tid >> 5, lane = tid & 31;
    for (int o = o0 + wid; o < o0 + 32; o += 8) {
        const float* pr = proj_w + (size_t)o * II;
        float wv[8];
        float ss = 0.f;
        #pragma unroll
        for (int m = 0; m < 8; m++) {
            float w = pr[lane + 32 * m] * sc[lane + 32 * m];
            wv[m] = w;
            ss += w * w;
        }
        #pragma unroll
        for (int off = 16; off; off >>= 1) ss += __shfl_xor_sync(0xffffffffu, ss, off);
        float d = rsqrtf(ss + 1e-8f);
        size_t base = ((size_t)b * OO + o) * II;
        #pragma unroll
        for (int m = 0; m < 8; m++)
            g_bw[base + lane + 32 * m] = __float2half_rn(wv[m] * d);
    }
}

// ---------------- kernel 3: fused conv + HMMA GEMM ----------------
__global__ void __launch_bounds__(NTHR, 1)
k_main(const float* __restrict__ bx, const float* __restrict__ conv_w,
       const float* __restrict__ proj_b, float* __restrict__ out) {
    extern __shared__ char smem[];
    const uint32_t sbu = smem_u32(smem);
    const int tid = threadIdx.x;
    const int wid = tid >> 5, lane = tid & 31;
    const int l0 = blockIdx.x * TN;
    const int b = blockIdx.y;
    const size_t bwb = (size_t)b * OO * II;

    // conv weights -> smem
    float* wc = (float*)(smem + SWC);
    for (int i = tid; i < II * KW; i += NTHR) wc[i] = conv_w[i];

    // ---- chunk loader: A tile (g_bw fp16) + bx rows, via cp.async ----
    auto issue_chunk = [&](int c, int buf) {
        const uint32_t sA = sbu + (buf ? SA1 : SA0);
        const __half* asrc = g_bw + bwb + c * KC;
        #pragma unroll
        for (int i = tid; i < 2048; i += NTHR) {      // 256 rows * 8 x 16B
            int m = i >> 3, q = i & 7;
            uint32_t off = m * 128 + q * 16;
            cp16(sA + SWZA(off), asrc + (size_t)m * II + q * 8, 16);
        }
        const uint32_t sX = sbu + (buf ? SX1 : SX0);
        const float* xsrc = bx + ((size_t)(b * II + c * KC)) * LL;
        for (int i = tid; i < 2176; i += NTHR) {      // 64 rows * 34 x 16B
            int r = i / 34, q = i - r * 34;
            int s = l0 - 4 + q * 4;
            bool ok = (s >= 0) && (s < LL);
            cp16(sX + r * 544 + q * 16, xsrc + (size_t)r * LL + (ok ? s : 0), ok ? 16 : 0);
        }
    };

    issue_chunk(0, 0);
    cp_commit();

    float acc[2][8][4];
    #pragma unroll
    for (int i = 0; i < 2; i++)
        #pragma unroll
        for (int j = 0; j < 8; j++)
            #pragma unroll
            for (int k = 0; k < 4; k++) acc[i][j][k] = 0.f;

    const int m0w = (wid & 7) * 32;    // warp M offset (A rows)
    const int n0w = (wid >> 3) * 64;   // warp N offset (L cols)

    for (int c = 0; c < NCH; c++) {
        const int buf = c & 1;
        cp_wait0();
        __syncthreads();

        // issue next chunk FIRST: overlaps its DRAM latency with conv + MMA.
        // Target buffer buf^1 was last read by MMA of chunk c-1, which
        // completed before the trailing __syncthreads of that iteration.
        if (c < NCH - 1) { issue_chunk(c + 1, buf ^ 1); cp_commit(); }

        // ---- conv: sbx (fp32) -> sB (fp16, k-major rows) ----
        {
            char* sBw = smem + (buf ? SB1 : SB0);
            const float* sbx = (const float*)(smem + (buf ? SX1 : SX0));
            const int n0 = lane * 4;              // output cols n0..n0+3
            #pragma unroll
            for (int cc = 0; cc < 4; cc++) {
                const int chl = wid * 4 + cc;     // 0..63
                const int chg = c * KC + chl;
                float cw[KW];
                #pragma unroll
                for (int j = 0; j < KW; j++) cw[j] = wc[chg * KW + j];
                const float4* r4 = (const float4*)(sbx + chl * 136);
                float4 q0 = r4[lane];             // sbx idx n0 .. n0+3
                float4 q1 = r4[lane + 1];         // n0+4 .. n0+7
                float4 q2 = r4[lane + 2];         // n0+8 .. n0+11
                float w[12] = {q0.x, q0.y, q0.z, q0.w, q1.x, q1.y, q1.z, q1.w,
                               q2.x, q2.y, q2.z, q2.w};
                // output n needs sbx idx (n+1 .. n+7)
                float a0 = 0.f, a1 = 0.f, a2 = 0.f, a3 = 0.f;
                #pragma unroll
                for (int j = 0; j < KW; j++) {
                    a0 += cw[j] * w[j + 1];
                    a1 += cw[j] * w[j + 2];
                    a2 += cw[j] * w[j + 3];
                    a3 += cw[j] * w[j + 4];
                }
                __half2 h01 = __halves2half2(__float2half_rn(a0), __float2half_rn(a1));
                __half2 h23 = __halves2half2(__float2half_rn(a2), __float2half_rn(a3));
                uint32_t off = (uint32_t)(chl * 256 + n0 * 2);
                uint2 v;
                v.x = *reinterpret_cast<uint32_t*>(&h01);
                v.y = *reinterpret_cast<uint32_t*>(&h23);
                *reinterpret_cast<uint2*>(sBw + (off ^ ((chl & 7) << 4))) = v;
            }
        }

        __syncthreads();

        // ---- MMA phase ----
        {
            const uint32_t sA = sbu + (buf ? SA1 : SA0);
            const uint32_t sBt = sbu + (buf ? SB1 : SB0);
            const int g = lane >> 3;       // ldmatrix address group 0..3
            const int li = lane & 7;
            #pragma unroll
            for (int ks = 0; ks < 4; ks++) {
                uint32_t afr[2][4];
                #pragma unroll
                for (int mt = 0; mt < 2; mt++) {
                    int row = m0w + mt * 16 + li + (g & 1) * 8;
                    int kh = ks * 16 + (g >> 1) * 8;
                    uint32_t off = row * 128 + kh * 2;
                    ldsm_x4(afr[mt], sA + SWZA(off));
                }
                uint32_t bfr[8][2];
                #pragma unroll
                for (int np = 0; np < 4; np++) {
                    int krow = ks * 16 + li + (g & 1) * 8;
                    int ncol = n0w + np * 16 + (g >> 1) * 8;
                    uint32_t off = krow * 256 + ncol * 2;
                    uint32_t r[4];
                    ldsm_x4_t(r, sBt + (off ^ ((krow & 7) << 4)));
                    bfr[2 * np][0] = r[0]; bfr[2 * np][1] = r[1];
                    bfr[2 * np + 1][0] = r[2]; bfr[2 * np + 1][1] = r[3];
                }
                #pragma unroll
                for (int mt = 0; mt < 2; mt++)
                    #pragma unroll
                    for (int nt = 0; nt < 8; nt++)
                        mma16816(acc[mt][nt], afr[mt], bfr[nt]);
            }
        }
        __syncthreads();
    }

    // ---- epilogue: direct float2 stores + bias ----
    const int rbase = m0w + (lane >> 2);
    const int cbase = n0w + 2 * (lane & 3);
    #pragma unroll
    for (int mt = 0; mt < 2; mt++) {
        int ra = rbase + mt * 16;
        int rb = ra + 8;
        float biasa = __ldg(proj_b + ra);
        float biasb = __ldg(proj_b + rb);
        float* pa = out + ((size_t)(b * OO + ra)) * LL + l0 + cbase;
        float* pb = out + ((size_t)(b * OO + rb)) * LL + l0 + cbase;
        #pragma unroll
        for (int nt = 0; nt < 8; nt++) {
            float2 v0 = {acc[mt][nt][0] + biasa, acc[mt][nt][1] + biasa};
            float2 v1 = {acc[mt][nt][2] + biasb, acc[mt][nt][3] + biasb};
            *reinterpret_cast<float2*>(pa + nt * 8) = v0;
            *reinterpret_cast<float2*>(pb + nt * 8) = v1;
        }
    }
}

// ---------------- launch ----------------
extern "C" void kernel_launch(void* const* d_in, const int* in_sizes, int n_in,
                              void* d_out, int out_size) {
    (void)in_sizes; (void)n_in; (void)out_size;
    const float* bx     = (const float*)d_in[0];
    const float* t      = (const float*)d_in[1];
    const float* conv_w = (const float*)d_in[2];
    const float* proj_w = (const float*)d_in[3];
    const float* proj_b = (const float*)d_in[4];
    const float* mod_w  = (const float*)d_in[5];
    const float* mod_b  = (const float*)d_in[6];
    float* out = (float*)d_out;

    cudaFuncSetAttribute(k_main, cudaFuncAttributeMaxDynamicSharedMemorySize, SM_TOTAL);

    k_scale<<<dim3(II / 8, BB), 256>>>(t, mod_w, mod_b);
    k_bw<<<dim3(OO / 32, BB), 256>>>(proj_w);
    k_main<<<dim3(LL / TN, BB), NTHR, SM_TOTAL>>>(bx, conv_w, proj_b, out);
}

// round 6
// speedup vs baseline: 1.4910x; 1.0349x over previous
#include <cuda_runtime.h>
#include <cuda_fp16.h>
#include <cstdint>

// ---------------- problem constants ----------------
static constexpr int BB = 16;
static constexpr int II = 256;   // in channels (= GEMM K)
static constexpr int OO = 256;   // out channels (= GEMM M)
static constexpr int TT = 512;
static constexpr int LL = 8192;  // length (= GEMM N)
static constexpr int KW = 7;

// ---------------- tiling ----------------
static constexpr int TN = 64;        // L per CTA
static constexpr int KC = 64;        // K chunk
static constexpr int NCH = II / KC;  // 4 chunks
static constexpr int NTHR = 256;     // 8 warps

// ---------------- smem layout (bytes) ----------------
// sA[2]: [256 m][64 k] fp16, 128B rows, SW128            2 x 32768
// sB:    [64 ch][64 n] fp16, 128B rows, SW128            1 x  8192
// sbx[2]: [64 ch][72 n] fp32 (l0-4 .. l0+67), 288B rows  2 x 18432
static constexpr int SA0 = 0;
static constexpr int SA1 = 32768;
static constexpr int SBQ = 65536;
static constexpr int SX0 = 73728;
static constexpr int SX1 = 92160;
static constexpr int SM_TOTAL = 110592;

// ---------------- device scratch ----------------
__device__ __half g_bw[(size_t)BB * OO * II];
__device__ float g_scale[BB * II];

// ---------------- helpers ----------------
__device__ __forceinline__ uint32_t smem_u32(const void* p) {
    uint32_t a;
    asm("{ .reg .u64 t; cvta.to.shared.u64 t, %1; cvt.u32.u64 %0, t; }" : "=r"(a) : "l"(p));
    return a;
}

__device__ __forceinline__ void cp16(uint32_t dst, const void* src, int sz) {
    asm volatile("cp.async.cg.shared.global [%0], [%1], 16, %2;"
                 :: "r"(dst), "l"(src), "r"(sz) : "memory");
}
__device__ __forceinline__ void cp_commit() {
    asm volatile("cp.async.commit_group;" ::: "memory");
}
__device__ __forceinline__ void cp_wait0() {
    asm volatile("cp.async.wait_group 0;" ::: "memory");
}
__device__ __forceinline__ void cp_wait1() {
    asm volatile("cp.async.wait_group 1;" ::: "memory");
}

__device__ __forceinline__ void ldsm_x4(uint32_t* r, uint32_t addr) {
    asm volatile("ldmatrix.sync.aligned.m8n8.x4.shared.b16 {%0,%1,%2,%3}, [%4];"
                 : "=r"(r[0]), "=r"(r[1]), "=r"(r[2]), "=r"(r[3]) : "r"(addr));
}
__device__ __forceinline__ void ldsm_x4_t(uint32_t* r, uint32_t addr) {
    asm volatile("ldmatrix.sync.aligned.m8n8.x4.trans.shared.b16 {%0,%1,%2,%3}, [%4];"
                 : "=r"(r[0]), "=r"(r[1]), "=r"(r[2]), "=r"(r[3]) : "r"(addr));
}

__device__ __forceinline__ void mma16816(float* c, const uint32_t* a, const uint32_t* b) {
    asm volatile(
        "mma.sync.aligned.m16n8k16.row.col.f32.f16.f16.f32 "
        "{%0,%1,%2,%3}, {%4,%5,%6,%7}, {%8,%9}, {%0,%1,%2,%3};"
        : "+f"(c[0]), "+f"(c[1]), "+f"(c[2]), "+f"(c[3])
        : "r"(a[0]), "r"(a[1]), "r"(a[2]), "r"(a[3]), "r"(b[0]), "r"(b[1]));
}

#define SWZA(off) ((off) ^ (((off) >> 3) & 0x70))

// ---------------- kernel 1: scale = t @ mod_w^T + mod_b + 1 ----------------
__global__ void k_scale(const float* __restrict__ t, const float* __restrict__ mod_w,
                        const float* __restrict__ mod_b) {
    const int b = blockIdx.y;
    const int i = blockIdx.x * 8 + (threadIdx.x >> 5);
    const int lane = threadIdx.x & 31;
    const float* tb = t + b * TT;
    const float* wr = mod_w + (size_t)i * TT;
    float s = 0.f;
    #pragma unroll
    for (int k = lane; k < TT; k += 32) s += tb[k] * wr[k];
    #pragma unroll
    for (int o = 16; o; o >>= 1) s += __shfl_xor_sync(0xffffffffu, s, o);
    if (lane == 0) g_scale[b * II + i] = s + mod_b[i] + 1.0f;
}

// ---------------- kernel 2: modulated + demodulated weights (fp16) ----------------
__global__ void k_bw(const float* __restrict__ proj_w) {
    int b = blockIdx.y;
    int o0 = blockIdx.x * 32;
    __shared__ float sc[II];
    int tid = threadIdx.x;
    if (tid < II) sc[tid] = g_scale[b * II + tid];
    __syncthreads();
    int wid = tid >> 5, lane = tid & 31;
    for (int o = o0 + wid; o < o0 + 32; o += 8) {
        const float* pr = proj_w + (size_t)o * II;
        float wv[8];
        float ss = 0.f;
        #pragma unroll
        for (int m = 0; m < 8; m++) {
            float w = pr[lane + 32 * m] * sc[lane + 32 * m];
            wv[m] = w;
            ss += w * w;
        }
        #pragma unroll
        for (int off = 16; off; off >>= 1) ss += __shfl_xor_sync(0xffffffffu, ss, off);
        float d = rsqrtf(ss + 1e-8f);
        size_t base = ((size_t)b * OO + o) * II;
        #pragma unroll
        for (int m = 0; m < 8; m++)
            g_bw[base + lane + 32 * m] = __float2half_rn(wv[m] * d);
    }
}

// ---------------- kernel 3: fused conv + HMMA GEMM, 2 CTAs/SM ----------------
__global__ void __launch_bounds__(NTHR, 2)
k_main(const float* __restrict__ bx, const float* __restrict__ conv_w,
       const float* __restrict__ proj_b, float* __restrict__ out) {
    extern __shared__ char smem[];
    const uint32_t sbu = smem_u32(smem);
    const int tid = threadIdx.x;
    const int wid = tid >> 5, lane = tid & 31;
    const int l0 = blockIdx.x * TN;
    const int b = blockIdx.y;
    const size_t bwb = (size_t)b * OO * II;

    // A tile for chunk c -> sA[c&1]
    auto issue_a = [&](int c) {
        const uint32_t sA = sbu + ((c & 1) ? SA1 : SA0);
        const __half* asrc = g_bw + bwb + c * KC;
        #pragma unroll
        for (int i = tid; i < 2048; i += NTHR) {   // 256 rows * 8 x 16B
            int m = i >> 3, q = i & 7;
            cp16(sA + SWZA(m * 128 + q * 16), asrc + (size_t)m * II + q * 8, 16);
        }
    };
    // bx rows for chunk c -> sbx[c&1]
    auto issue_x = [&](int c) {
        const uint32_t sX = sbu + ((c & 1) ? SX1 : SX0);
        const float* xsrc = bx + ((size_t)(b * II + c * KC)) * LL;
        for (int i = tid; i < 1152; i += NTHR) {   // 64 rows * 18 x 16B
            int r = i / 18, q = i - r * 18;
            int s = l0 - 4 + q * 4;
            bool ok = (s >= 0) && (s < LL);
            cp16(sX + r * 288 + q * 16, xsrc + (size_t)r * LL + (ok ? s : 0), ok ? 16 : 0);
        }
    };

    // prologue: bx0 | A0 | bx1 (3 groups pending)
    issue_x(0); cp_commit();
    issue_a(0); cp_commit();
    issue_x(1); cp_commit();

    float acc[2][8][4];
    #pragma unroll
    for (int i = 0; i < 2; i++)
        #pragma unroll
        for (int j = 0; j < 8; j++)
            #pragma unroll
            for (int k = 0; k < 4; k++) acc[i][j][k] = 0.f;

    const int m0w = wid * 32;   // warp M offset; all warps cover full N=64

    for (int c = 0; c < NCH; c++) {
        const int buf = c & 1;
        // complete {bx(c), A(c)}; keep bx(c+1) in flight
        if (c < NCH - 1) cp_wait1(); else cp_wait0();
        __syncthreads();

        // prefetch A(c+1) now: sA[buf^1] was last read by MMA(c-1), done.
        if (c < NCH - 1) { issue_a(c + 1); cp_commit(); }

        // ---- conv: sbx[buf] (fp32) -> sB (fp16, 128B rows, SW128) ----
        {
            char* sBw = smem + SBQ;
            const float* sbx = (const float*)(smem + (buf ? SX1 : SX0));
            const int n0 = (lane & 15) * 4;       // 4 outputs per lane
            const int hsel = lane >> 4;           // 2 channels per pass
            #pragma unroll
            for (int cc = 0; cc < 4; cc++) {
                const int chl = wid * 8 + cc * 2 + hsel;   // 0..63
                const int chg = c * KC + chl;
                float cw[KW];
                #pragma unroll
                for (int j = 0; j < KW; j++) cw[j] = __ldg(conv_w + chg * KW + j);
                const float4* r4 = (const float4*)(sbx + chl * 72);
                float4 q0 = r4[(lane & 15)];
                float4 q1 = r4[(lane & 15) + 1];
                float4 q2 = r4[(lane & 15) + 2];
                float w[12] = {q0.x, q0.y, q0.z, q0.w, q1.x, q1.y, q1.z, q1.w,
                               q2.x, q2.y, q2.z, q2.w};
                float a0 = 0.f, a1 = 0.f, a2 = 0.f, a3 = 0.f;
                #pragma unroll
                for (int j = 0; j < KW; j++) {
                    a0 += cw[j] * w[j + 1];
                    a1 += cw[j] * w[j + 2];
                    a2 += cw[j] * w[j + 3];
                    a3 += cw[j] * w[j + 4];
                }
                __half2 h01 = __halves2half2(__float2half_rn(a0), __float2half_rn(a1));
                __half2 h23 = __halves2half2(__float2half_rn(a2), __float2half_rn(a3));
                uint32_t off = (uint32_t)(chl * 128 + n0 * 2);
                uint2 v;
                v.x = *reinterpret_cast<uint32_t*>(&h01);
                v.y = *reinterpret_cast<uint32_t*>(&h23);
                *reinterpret_cast<uint2*>(sBw + SWZA(off)) = v;
            }
        }
        __syncthreads();

        // sbx[buf] consumed -> prefetch bx(c+2) into it
        if (c < NCH - 2) { issue_x(c + 2); cp_commit(); }

        // ---- MMA phase ----
        {
            const uint32_t sA = sbu + (buf ? SA1 : SA0);
            const uint32_t sBt = sbu + SBQ;
            const int g = lane >> 3;
            const int li = lane & 7;
            #pragma unroll
            for (int ks = 0; ks < 4; ks++) {
                uint32_t afr[2][4];
                #pragma unroll
                for (int mt = 0; mt < 2; mt++) {
                    int row = m0w + mt * 16 + li + (g & 1) * 8;
                    int kh = ks * 16 + (g >> 1) * 8;
                    ldsm_x4(afr[mt], sA + SWZA((uint32_t)(row * 128 + kh * 2)));
                }
                uint32_t bfr[8][2];
                #pragma unroll
                for (int np = 0; np < 4; np++) {
                    int krow = ks * 16 + li + (g & 1) * 8;
                    int ncol = np * 16 + (g >> 1) * 8;
                    uint32_t r[4];
                    ldsm_x4_t(r, sBt + SWZA((uint32_t)(krow * 128 + ncol * 2)));
                    bfr[2 * np][0] = r[0]; bfr[2 * np][1] = r[1];
                    bfr[2 * np + 1][0] = r[2]; bfr[2 * np + 1][1] = r[3];
                }
                #pragma unroll
                for (int mt = 0; mt < 2; mt++)
                    #pragma unroll
                    for (int nt = 0; nt < 8; nt++)
                        mma16816(acc[mt][nt], afr[mt], bfr[nt]);
            }
        }
        __syncthreads();   // sB reuse by next conv; sA[buf] reuse by A(c+2)
    }

    // ---- epilogue: direct float2 stores + bias ----
    const int rbase = m0w + (lane >> 2);
    const int cbase = 2 * (lane & 3);
    #pragma unroll
    for (int mt = 0; mt < 2; mt++) {
        int ra = rbase + mt * 16;
        int rb = ra + 8;
        float biasa = __ldg(proj_b + ra);
        float biasb = __ldg(proj_b + rb);
        float* pa = out + ((size_t)(b * OO + ra)) * LL + l0 + cbase;
        float* pb = out + ((size_t)(b * OO + rb)) * LL + l0 + cbase;
        #pragma unroll
        for (int nt = 0; nt < 8; nt++) {
            float2 v0 = {acc[mt][nt][0] + biasa, acc[mt][nt][1] + biasa};
            float2 v1 = {acc[mt][nt][2] + biasb, acc[mt][nt][3] + biasb};
            *reinterpret_cast<float2*>(pa + nt * 8) = v0;
            *reinterpret_cast<float2*>(pb + nt * 8) = v1;
        }
    }
}

// ---------------- launch ----------------
extern "C" void kernel_launch(void* const* d_in, const int* in_sizes, int n_in,
                              void* d_out, int out_size) {
    (void)in_sizes; (void)n_in; (void)out_size;
    const float* bx     = (const float*)d_in[0];
    const float* t      = (const float*)d_in[1];
    const float* conv_w = (const float*)d_in[2];
    const float* proj_w = (const float*)d_in[3];
    const float* proj_b = (const float*)d_in[4];
    const float* mod_w  = (const float*)d_in[5];
    const float* mod_b  = (const float*)d_in[6];
    float* out = (float*)d_out;

    cudaFuncSetAttribute(k_main, cudaFuncAttributeMaxDynamicSharedMemorySize, SM_TOTAL);

    k_scale<<<dim3(II / 8, BB), 256>>>(t, mod_w, mod_b);
    k_bw<<<dim3(OO / 32, BB), 256>>>(proj_w);
    k_main<<<dim3(LL / TN, BB), NTHR, SM_TOTAL>>>(bx, conv_w, proj_b, out);
}